// round 4
// baseline (speedup 1.0000x reference)
#include <cuda_runtime.h>
#include <cuda_bf16.h>

// Problem constants (validated against in_sizes at runtime; buffers sized to max)
#define MAXN 100000
#define MAXE 600000
#define D 128
#define L_LAYERS 5
#define NPART 296   // pool partial blocks

// ---------------- scratch (device globals; no allocation allowed) -------------
__device__ float g_bufA[MAXN * D];        // 51.2 MB
__device__ float g_bufB[MAXN * D];        // 51.2 MB
__device__ int   g_deg[MAXN];
__device__ int   g_rowptr[MAXN + 1];
__device__ int   g_cursor[MAXN];
__device__ int   g_col[MAXE];
__device__ float g_part[NPART * D];

// ---------------- small utility kernels --------------------------------------
__global__ void k_zero_int(int* __restrict__ p, int n) {
    int i = blockIdx.x * blockDim.x + threadIdx.x;
    if (i < n) p[i] = 0;
}

__global__ void k_copy_int(const int* __restrict__ a, int* __restrict__ b, int n) {
    int i = blockIdx.x * blockDim.x + threadIdx.x;
    if (i < n) b[i] = a[i];
}

// h[n,:] = emb[x[n],:]   (one float4 per thread)
__global__ void k_gather(const int* __restrict__ x, const float* __restrict__ emb,
                         float* __restrict__ h, int n) {
    int i = blockIdx.x * blockDim.x + threadIdx.x;   // over n*32 float4s
    if (i < n * (D / 4)) {
        int node = i >> 5;            // D/4 = 32
        int q    = i & 31;
        reinterpret_cast<float4*>(h)[(size_t)node * 32 + q] =
            reinterpret_cast<const float4*>(emb)[(size_t)x[node] * 32 + q];
    }
}

// degree histogram over dst
__global__ void k_count(const int* __restrict__ dst, int* __restrict__ deg, int e) {
    int i = blockIdx.x * blockDim.x + threadIdx.x;
    if (i < e) atomicAdd(&deg[dst[i]], 1);
}

// single-block exclusive scan (Hillis-Steele per 1024 tile + running carry)
__global__ void k_scan(const int* __restrict__ deg, int* __restrict__ rowptr, int n) {
    __shared__ int s[1024];
    __shared__ int carry;
    if (threadIdx.x == 0) carry = 0;
    for (int base = 0; base < n; base += 1024) {
        __syncthreads();                        // carry from prev tile visible
        int i = base + threadIdx.x;
        int v = (i < n) ? deg[i] : 0;
        s[threadIdx.x] = v;
        __syncthreads();
        for (int off = 1; off < 1024; off <<= 1) {
            int t = (threadIdx.x >= (unsigned)off) ? s[threadIdx.x - off] : 0;
            __syncthreads();
            s[threadIdx.x] += t;
            __syncthreads();
        }
        if (i < n) rowptr[i] = carry + s[threadIdx.x] - v;   // exclusive
        __syncthreads();                        // everyone done reading carry
        if (threadIdx.x == 0) carry += s[1023];
    }
    __syncthreads();
    if (threadIdx.x == 0) rowptr[n] = carry;
}

// bucket edges by dst:  col[cursor[dst]++] = src
__global__ void k_scatter(const int* __restrict__ src, const int* __restrict__ dst,
                          int* __restrict__ cursor, int* __restrict__ col, int e) {
    int i = blockIdx.x * blockDim.x + threadIdx.x;
    if (i < e) {
        int d = dst[i];
        int p = atomicAdd(&cursor[d], 1);
        col[p] = src[i];
    }
}

// z[n,:] = h[n,:] + sum_{j in CSR[n]} h[col[j],:]   — one block (128 thr) per node
__global__ void k_agg(const float* __restrict__ h, const int* __restrict__ rowptr,
                      const int* __restrict__ col, float* __restrict__ z) {
    int n = blockIdx.x;
    int d = threadIdx.x;
    float acc = h[(size_t)n * D + d];
    int s0 = rowptr[n], s1 = rowptr[n + 1];
    for (int j = s0; j < s1; j++) {
        int c = __ldg(&col[j]);
        acc += __ldg(&h[(size_t)c * D + d]);
    }
    z[(size_t)n * D + d] = acc;
}

// C[N,128] = relu(Z[N,128] @ W[128,128] + bias)
// 256 threads, 128-row block tile, full 128-col span, 8x8 thread microtile, BK=32
__global__ __launch_bounds__(256)
void k_gemm_bias_relu(const float* __restrict__ Z, const float* __restrict__ W,
                      const float* __restrict__ bias, float* __restrict__ C, int n) {
    __shared__ float Ws[32][128];       // W[k][c]
    __shared__ float Zs[32][132];       // Z transposed: Zs[k][row], padded

    const int tid = threadIdx.x;
    const int tr = tid >> 4, tc = tid & 15;       // 16x16 thread grid
    const int r0 = tr * 8, c0 = tc * 8;
    const int rowBase = blockIdx.x * 128;

    float acc[8][8];
#pragma unroll
    for (int i = 0; i < 8; i++)
#pragma unroll
        for (int j = 0; j < 8; j++) acc[i][j] = 0.0f;

    for (int kt = 0; kt < 128; kt += 32) {
        // load W tile: 32x128 floats = 1024 float4, 4 per thread
#pragma unroll
        for (int it = 0; it < 4; it++) {
            int li = tid + it * 256;            // 0..1023
            int k = li >> 5, q = li & 31;
            float4 v = *reinterpret_cast<const float4*>(W + (kt + k) * 128 + q * 4);
            *reinterpret_cast<float4*>(&Ws[k][q * 4]) = v;
        }
        // load Z tile (transpose into Zs): 128 rows x 32 k
#pragma unroll
        for (int it = 0; it < 4; it++) {
            int li = tid + it * 256;            // 0..1023
            int row = li >> 3, q = li & 7;      // q: float4 within 32 k
            int gr = rowBase + row;
            float4 v = make_float4(0.f, 0.f, 0.f, 0.f);
            if (gr < n)
                v = *reinterpret_cast<const float4*>(Z + (size_t)gr * 128 + kt + q * 4);
            Zs[q * 4 + 0][row] = v.x;
            Zs[q * 4 + 1][row] = v.y;
            Zs[q * 4 + 2][row] = v.z;
            Zs[q * 4 + 3][row] = v.w;
        }
        __syncthreads();
#pragma unroll 8
        for (int k = 0; k < 32; k++) {
            float a[8], b[8];
            *reinterpret_cast<float4*>(a)     = *reinterpret_cast<float4*>(&Zs[k][r0]);
            *reinterpret_cast<float4*>(a + 4) = *reinterpret_cast<float4*>(&Zs[k][r0 + 4]);
            *reinterpret_cast<float4*>(b)     = *reinterpret_cast<float4*>(&Ws[k][c0]);
            *reinterpret_cast<float4*>(b + 4) = *reinterpret_cast<float4*>(&Ws[k][c0 + 4]);
#pragma unroll
            for (int i = 0; i < 8; i++)
#pragma unroll
                for (int j = 0; j < 8; j++)
                    acc[i][j] = fmaf(a[i], b[j], acc[i][j]);
        }
        __syncthreads();
    }

    float bv[8];
    *reinterpret_cast<float4*>(bv)     = *reinterpret_cast<const float4*>(bias + c0);
    *reinterpret_cast<float4*>(bv + 4) = *reinterpret_cast<const float4*>(bias + c0 + 4);

#pragma unroll
    for (int i = 0; i < 8; i++) {
        int gr = rowBase + r0 + i;
        if (gr < n) {
            float4 o1, o2;
            o1.x = fmaxf(acc[i][0] + bv[0], 0.f);
            o1.y = fmaxf(acc[i][1] + bv[1], 0.f);
            o1.z = fmaxf(acc[i][2] + bv[2], 0.f);
            o1.w = fmaxf(acc[i][3] + bv[3], 0.f);
            o2.x = fmaxf(acc[i][4] + bv[4], 0.f);
            o2.y = fmaxf(acc[i][5] + bv[5], 0.f);
            o2.z = fmaxf(acc[i][6] + bv[6], 0.f);
            o2.w = fmaxf(acc[i][7] + bv[7], 0.f);
            *reinterpret_cast<float4*>(C + (size_t)gr * 128 + c0)     = o1;
            *reinterpret_cast<float4*>(C + (size_t)gr * 128 + c0 + 4) = o2;
        }
    }
}

// deterministic column-sum partials: part[b, d] = sum over its row stripe
__global__ void k_pool_partial(const float* __restrict__ h, float* __restrict__ part, int n) {
    int d = threadIdx.x;              // 128 threads
    float acc = 0.f;
    for (int r = blockIdx.x; r < n; r += gridDim.x)
        acc += h[(size_t)r * D + d];
    part[blockIdx.x * D + d] = acc;
}

// out[o] = blin[o] + sum_d pooled[d] * Wlin[d][o], pooled reduced from partials
__global__ void k_final(const float* __restrict__ part, const float* __restrict__ Wlin,
                        const float* __restrict__ blin, float* __restrict__ out) {
    __shared__ float pooled[D];
    int t = threadIdx.x;              // 128 threads
    float acc = 0.f;
    for (int p = 0; p < NPART; p++) acc += part[p * D + t];
    pooled[t] = acc;
    __syncthreads();
    float o = blin[t];
    for (int d = 0; d < D; d++) o = fmaf(pooled[d], Wlin[d * D + t], o);
    out[t] = o;
}

// ---------------- launch -------------------------------------------------------
extern "C" void kernel_launch(void* const* d_in, const int* in_sizes, int n_in,
                              void* d_out, int out_size) {
    const int*   x    = (const int*)d_in[0];
    const int*   ei   = (const int*)d_in[1];
    const float* emb  = (const float*)d_in[2];
    const float* Wa   = (const float*)d_in[3];
    const float* ba   = (const float*)d_in[4];
    const float* Wb   = (const float*)d_in[5];
    const float* bb   = (const float*)d_in[6];
    const float* Wlin = (const float*)d_in[7];
    const float* blin = (const float*)d_in[8];
    float* out = (float*)d_out;

    const int N = in_sizes[0];
    const int E = in_sizes[1] / 2;
    const int* src = ei;
    const int* dst = ei + E;

    float *A, *B, *part;
    int *deg, *rowptr, *cursor, *col;
    cudaGetSymbolAddress((void**)&A, g_bufA);
    cudaGetSymbolAddress((void**)&B, g_bufB);
    cudaGetSymbolAddress((void**)&deg, g_deg);
    cudaGetSymbolAddress((void**)&rowptr, g_rowptr);
    cudaGetSymbolAddress((void**)&cursor, g_cursor);
    cudaGetSymbolAddress((void**)&col, g_col);
    cudaGetSymbolAddress((void**)&part, g_part);

    // h = emb[x]
    k_gather<<<(N * 32 + 255) / 256, 256>>>(x, emb, A, N);

    // build CSR (dst-bucketed adjacency) once per launch
    k_zero_int<<<(N + 255) / 256, 256>>>(deg, N);
    k_count<<<(E + 255) / 256, 256>>>(dst, deg, E);
    k_scan<<<1, 1024>>>(deg, rowptr, N);
    k_copy_int<<<(N + 255) / 256, 256>>>(rowptr, cursor, N);
    k_scatter<<<(E + 255) / 256, 256>>>(src, dst, cursor, col, E);

    const int gemm_blocks = (N + 127) / 128;
    for (int l = 0; l < L_LAYERS; l++) {
        k_agg<<<N, 128>>>(A, rowptr, col, B);                                   // B = A + agg(A)
        k_gemm_bias_relu<<<gemm_blocks, 256>>>(B, Wa + l * D * D, ba + l * D, A, N); // A = relu(B@Wa+ba)
        k_gemm_bias_relu<<<gemm_blocks, 256>>>(A, Wb + l * D * D, bb + l * D, B, N); // B = relu(A@Wb+bb)
        float* t = A; A = B; B = t;                                             // h now in A
    }

    // global add pool + final linear
    k_pool_partial<<<NPART, 128>>>(A, part, N);
    k_final<<<1, 128>>>(part, Wlin, blin, out);
}

// round 8
// speedup vs baseline: 1.1609x; 1.1609x over previous
#include <cuda_runtime.h>
#include <cuda_bf16.h>

// Problem constants
#define MAXN 100000
#define MAXE 600000
#define D 128
#define L_LAYERS 5
#define NPART 296
#define SCAN_BLK 1024

// ---------------- scratch (device globals; no allocation allowed) -------------
__device__ float g_bufA[MAXN * D];
__device__ float g_bufB[MAXN * D];
__device__ int   g_deg[MAXN];
__device__ int   g_rowptr[MAXN + 1];
__device__ int   g_cursor[MAXN];
__device__ int   g_col[MAXE];
__device__ float g_part[NPART * D];
__device__ int   g_bsum[128];
__device__ int   g_boff[128];

// ---------------- utility kernels --------------------------------------------
__global__ void k_zero_int(int* __restrict__ p, int n) {
    int i = blockIdx.x * blockDim.x + threadIdx.x;
    if (i < n) p[i] = 0;
}

// h[n,:] = emb[x[n],:]
__global__ void k_gather(const int* __restrict__ x, const float* __restrict__ emb,
                         float* __restrict__ h, int n) {
    int i = blockIdx.x * blockDim.x + threadIdx.x;
    if (i < n * (D / 4)) {
        int node = i >> 5;
        int q    = i & 31;
        reinterpret_cast<float4*>(h)[(size_t)node * 32 + q] =
            reinterpret_cast<const float4*>(emb)[(size_t)x[node] * 32 + q];
    }
}

__global__ void k_count(const int* __restrict__ dst, int* __restrict__ deg, int e) {
    int i = blockIdx.x * blockDim.x + threadIdx.x;
    if (i < e) atomicAdd(&deg[dst[i]], 1);
}

// ---- 3-phase scan -------------------------------------------------------------
// Phase 1: per-block exclusive scan (local), block totals to bsum
__global__ void k_scan_blk(const int* __restrict__ deg, int* __restrict__ rowptr,
                           int* __restrict__ bsum, int n) {
    int i = blockIdx.x * SCAN_BLK + threadIdx.x;
    int lane = threadIdx.x & 31, wid = threadIdx.x >> 5;
    int v = (i < n) ? deg[i] : 0;
    int inc = v;
#pragma unroll
    for (int o = 1; o < 32; o <<= 1) {
        int t = __shfl_up_sync(0xFFFFFFFFu, inc, o);
        if (lane >= o) inc += t;
    }
    __shared__ int wsum[32];
    if (lane == 31) wsum[wid] = inc;
    __syncthreads();
    if (wid == 0) {
        int s = wsum[lane];
#pragma unroll
        for (int o = 1; o < 32; o <<= 1) {
            int t = __shfl_up_sync(0xFFFFFFFFu, s, o);
            if (lane >= o) s += t;
        }
        wsum[lane] = s;     // inclusive warp sums
    }
    __syncthreads();
    int base = (wid > 0) ? wsum[wid - 1] : 0;
    if (i < n) rowptr[i] = base + inc - v;          // local exclusive
    if (threadIdx.x == SCAN_BLK - 1) bsum[blockIdx.x] = base + inc;  // block total
}

// Phase 2: scan block totals (nb <= 128) with 128 threads; total to *total_out
__global__ void k_scan_top(const int* __restrict__ bsum, int* __restrict__ boff,
                           int* __restrict__ total_out, int nb) {
    int t = threadIdx.x, lane = t & 31, wid = t >> 5;
    int v = (t < nb) ? bsum[t] : 0;
    int inc = v;
#pragma unroll
    for (int o = 1; o < 32; o <<= 1) {
        int u = __shfl_up_sync(0xFFFFFFFFu, inc, o);
        if (lane >= o) inc += u;
    }
    __shared__ int ws[32];
    __shared__ int wsx[33];
    if (lane == 31) ws[wid] = inc;
    __syncthreads();
    if (t == 0) {
        wsx[0] = 0;
        for (int w = 0; w < 4; w++) wsx[w + 1] = wsx[w] + ws[w];
    }
    __syncthreads();
    int excl = wsx[wid] + inc - v;
    if (t < nb) boff[t] = excl;
    if (t == blockDim.x - 1) *total_out = wsx[4];
}

// Phase 3: add block offsets; write final rowptr and cursor
__global__ void k_scan_add(int* __restrict__ rowptr, int* __restrict__ cursor,
                           const int* __restrict__ boff, int n) {
    int i = blockIdx.x * blockDim.x + threadIdx.x;
    if (i < n) {
        int r = rowptr[i] + boff[i >> 10];
        rowptr[i] = r;
        cursor[i] = r;
    }
}

__global__ void k_scatter(const int* __restrict__ src, const int* __restrict__ dst,
                          int* __restrict__ cursor, int* __restrict__ col, int e) {
    int i = blockIdx.x * blockDim.x + threadIdx.x;
    if (i < e) {
        int d = dst[i];
        int p = atomicAdd(&cursor[d], 1);
        col[p] = src[i];
    }
}

// z[n,:] = h[n,:] + sum neighbors — 4 nodes per 128-thread block, float4, unroll-2
__global__ void k_agg(const float* __restrict__ h, const int* __restrict__ rowptr,
                      const int* __restrict__ col, float* __restrict__ z, int n) {
    int node = blockIdx.x * 4 + (threadIdx.x >> 5);
    if (node >= n) return;
    int lane = threadIdx.x & 31;
    const float4* h4 = reinterpret_cast<const float4*>(h);
    float4 acc = h4[(size_t)node * 32 + lane];
    int s0 = rowptr[node], s1 = rowptr[node + 1];
    int j = s0;
    for (; j + 1 < s1; j += 2) {
        int c0 = __ldg(&col[j]), c1 = __ldg(&col[j + 1]);
        float4 v0 = __ldg(&h4[(size_t)c0 * 32 + lane]);
        float4 v1 = __ldg(&h4[(size_t)c1 * 32 + lane]);
        acc.x += v0.x + v1.x; acc.y += v0.y + v1.y;
        acc.z += v0.z + v1.z; acc.w += v0.w + v1.w;
    }
    if (j < s1) {
        int c = __ldg(&col[j]);
        float4 v = __ldg(&h4[(size_t)c * 32 + lane]);
        acc.x += v.x; acc.y += v.y; acc.z += v.z; acc.w += v.w;
    }
    reinterpret_cast<float4*>(z)[(size_t)node * 32 + lane] = acc;
}

// C[N,128] = relu(Z @ W + bias)  — packed fma.rn.f32x2 microkernel
// 256 threads, 128-row tile, BK=16, 8x8 microtile as 8x(4 pairs)
__global__ __launch_bounds__(256)
void k_gemm_bias_relu(const float* __restrict__ Z, const float* __restrict__ W,
                      const float* __restrict__ bias, float* __restrict__ C, int n) {
    __shared__ float Ws[16][128];        // 8 KB
    __shared__ float Zsd[16][260];       // duplicated rows, 16.25 KB

    const int tid = threadIdx.x;
    const int tr = tid >> 4, tc = tid & 15;
    const int r0 = tr * 8, c0 = tc * 8;
    const int rowBase = blockIdx.x * 128;

    unsigned long long acc2[8][4];
#pragma unroll
    for (int i = 0; i < 8; i++)
#pragma unroll
        for (int j = 0; j < 4; j++) acc2[i][j] = 0ull;

    for (int kt = 0; kt < 128; kt += 16) {
        // W tile: 16x128 floats = 512 float4, 2 per thread
#pragma unroll
        for (int it = 0; it < 2; it++) {
            int li = tid + it * 256;
            int k = li >> 5, q = li & 31;
            *reinterpret_cast<float4*>(&Ws[k][q * 4]) =
                *reinterpret_cast<const float4*>(W + (kt + k) * 128 + q * 4);
        }
        // Z tile: 128 rows x 16 k, duplicated into Zsd[k][2r]=Zsd[k][2r+1]
#pragma unroll
        for (int it = 0; it < 2; it++) {
            int li = tid + it * 256;
            int row = li >> 2, q = li & 3;
            int gr = rowBase + row;
            float4 v = make_float4(0.f, 0.f, 0.f, 0.f);
            if (gr < n)
                v = *reinterpret_cast<const float4*>(Z + (size_t)gr * 128 + kt + q * 4);
            int k = q * 4;
            *reinterpret_cast<float2*>(&Zsd[k + 0][2 * row]) = make_float2(v.x, v.x);
            *reinterpret_cast<float2*>(&Zsd[k + 1][2 * row]) = make_float2(v.y, v.y);
            *reinterpret_cast<float2*>(&Zsd[k + 2][2 * row]) = make_float2(v.z, v.z);
            *reinterpret_cast<float2*>(&Zsd[k + 3][2 * row]) = make_float2(v.w, v.w);
        }
        __syncthreads();
#pragma unroll
        for (int k = 0; k < 16; k++) {
            ulonglong2 A01 = *reinterpret_cast<const ulonglong2*>(&Zsd[k][2 * r0]);
            ulonglong2 A23 = *reinterpret_cast<const ulonglong2*>(&Zsd[k][2 * r0 + 4]);
            ulonglong2 A45 = *reinterpret_cast<const ulonglong2*>(&Zsd[k][2 * r0 + 8]);
            ulonglong2 A67 = *reinterpret_cast<const ulonglong2*>(&Zsd[k][2 * r0 + 12]);
            ulonglong2 B01 = *reinterpret_cast<const ulonglong2*>(&Ws[k][c0]);
            ulonglong2 B23 = *reinterpret_cast<const ulonglong2*>(&Ws[k][c0 + 4]);
            unsigned long long a[8] = {A01.x, A01.y, A23.x, A23.y,
                                       A45.x, A45.y, A67.x, A67.y};
            unsigned long long b[4] = {B01.x, B01.y, B23.x, B23.y};
#pragma unroll
            for (int i = 0; i < 8; i++)
#pragma unroll
                for (int j = 0; j < 4; j++)
                    asm("fma.rn.f32x2 %0, %1, %2, %0;"
                        : "+l"(acc2[i][j]) : "l"(a[i]), "l"(b[j]));
        }
        __syncthreads();
    }

    float bv[8];
    *reinterpret_cast<float4*>(bv)     = *reinterpret_cast<const float4*>(bias + c0);
    *reinterpret_cast<float4*>(bv + 4) = *reinterpret_cast<const float4*>(bias + c0 + 4);

#pragma unroll
    for (int i = 0; i < 8; i++) {
        int gr = rowBase + r0 + i;
        if (gr >= n) continue;
        float o[8];
#pragma unroll
        for (int j = 0; j < 4; j++) {
            float lo, hi;
            asm("mov.b64 {%0, %1}, %2;" : "=f"(lo), "=f"(hi) : "l"(acc2[i][j]));
            o[2 * j]     = fmaxf(lo + bv[2 * j], 0.f);
            o[2 * j + 1] = fmaxf(hi + bv[2 * j + 1], 0.f);
        }
        *reinterpret_cast<float4*>(C + (size_t)gr * 128 + c0) =
            make_float4(o[0], o[1], o[2], o[3]);
        *reinterpret_cast<float4*>(C + (size_t)gr * 128 + c0 + 4) =
            make_float4(o[4], o[5], o[6], o[7]);
    }
}

// deterministic pool partials
__global__ void k_pool_partial(const float* __restrict__ h, float* __restrict__ part, int n) {
    int d = threadIdx.x;
    float acc = 0.f;
    for (int r = blockIdx.x; r < n; r += gridDim.x)
        acc += h[(size_t)r * D + d];
    part[blockIdx.x * D + d] = acc;
}

__global__ void k_final(const float* __restrict__ part, const float* __restrict__ Wlin,
                        const float* __restrict__ blin, float* __restrict__ out) {
    __shared__ float pooled[D];
    int t = threadIdx.x;
    float acc = 0.f;
    for (int p = 0; p < NPART; p++) acc += part[p * D + t];
    pooled[t] = acc;
    __syncthreads();
    float o = blin[t];
    for (int d = 0; d < D; d++) o = fmaf(pooled[d], Wlin[d * D + t], o);
    out[t] = o;
}

// ---------------- launch -------------------------------------------------------
extern "C" void kernel_launch(void* const* d_in, const int* in_sizes, int n_in,
                              void* d_out, int out_size) {
    const int*   x    = (const int*)d_in[0];
    const int*   ei   = (const int*)d_in[1];
    const float* emb  = (const float*)d_in[2];
    const float* Wa   = (const float*)d_in[3];
    const float* ba   = (const float*)d_in[4];
    const float* Wb   = (const float*)d_in[5];
    const float* bb   = (const float*)d_in[6];
    const float* Wlin = (const float*)d_in[7];
    const float* blin = (const float*)d_in[8];
    float* out = (float*)d_out;

    const int N = in_sizes[0];
    const int E = in_sizes[1] / 2;
    const int* src = ei;
    const int* dst = ei + E;

    float *A, *B, *part;
    int *deg, *rowptr, *cursor, *col, *bsum, *boff;
    cudaGetSymbolAddress((void**)&A, g_bufA);
    cudaGetSymbolAddress((void**)&B, g_bufB);
    cudaGetSymbolAddress((void**)&deg, g_deg);
    cudaGetSymbolAddress((void**)&rowptr, g_rowptr);
    cudaGetSymbolAddress((void**)&cursor, g_cursor);
    cudaGetSymbolAddress((void**)&col, g_col);
    cudaGetSymbolAddress((void**)&part, g_part);
    cudaGetSymbolAddress((void**)&bsum, g_bsum);
    cudaGetSymbolAddress((void**)&boff, g_boff);

    // h = emb[x]
    k_gather<<<(N * 32 + 255) / 256, 256>>>(x, emb, A, N);

    // CSR build
    k_zero_int<<<(N + 255) / 256, 256>>>(deg, N);
    k_count<<<(E + 255) / 256, 256>>>(dst, deg, E);
    const int nb = (N + SCAN_BLK - 1) / SCAN_BLK;
    k_scan_blk<<<nb, SCAN_BLK>>>(deg, rowptr, bsum, N);
    k_scan_top<<<1, 128>>>(bsum, boff, rowptr + N, nb);
    k_scan_add<<<(N + 255) / 256, 256>>>(rowptr, cursor, boff, N);
    k_scatter<<<(E + 255) / 256, 256>>>(src, dst, cursor, col, E);

    const int gemm_blocks = (N + 127) / 128;
    const int agg_blocks  = (N + 3) / 4;
    for (int l = 0; l < L_LAYERS; l++) {
        k_agg<<<agg_blocks, 128>>>(A, rowptr, col, B, N);
        k_gemm_bias_relu<<<gemm_blocks, 256>>>(B, Wa + l * D * D, ba + l * D, A, N);
        k_gemm_bias_relu<<<gemm_blocks, 256>>>(A, Wb + l * D * D, bb + l * D, B, N);
        float* t = A; A = B; B = t;
    }

    k_pool_partial<<<NPART, 128>>>(A, part, N);
    k_final<<<1, 128>>>(part, Wlin, blin, out);
}

// round 10
// speedup vs baseline: 1.5572x; 1.3414x over previous
#include <cuda_runtime.h>
#include <cuda_bf16.h>
#include <cstdint>

// Problem constants
#define MAXN 100000
#define MAXE 600000
#define D 128
#define L_LAYERS 5
#define NPART 296
#define SCAN_BLK 1024

// ---------------- scratch (device globals; no allocation allowed) -------------
__device__ float g_bufA[MAXN * D];
__device__ float g_bufB[MAXN * D];
__device__ int   g_deg[MAXN];
__device__ int   g_rowptr[MAXN + 1];
__device__ int   g_cursor[MAXN];
__device__ int   g_col[MAXE];
__device__ float g_part[NPART * D];
__device__ int   g_bsum[128];
__device__ int   g_boff[128];
// pre-split transposed weights: 10 matrices x 128x128 bf16 (as uint4)
__device__ uint4 g_WhiT[10 * 128 * 128 / 8];
__device__ uint4 g_WloT[10 * 128 * 128 / 8];

// ---------------- utility kernels --------------------------------------------
__global__ void k_zero_int(int* __restrict__ p, int n) {
    int i = blockIdx.x * blockDim.x + threadIdx.x;
    if (i < n) p[i] = 0;
}

__global__ void k_gather(const int* __restrict__ x, const float* __restrict__ emb,
                         float* __restrict__ h, int n) {
    int i = blockIdx.x * blockDim.x + threadIdx.x;
    if (i < n * (D / 4)) {
        int node = i >> 5;
        int q    = i & 31;
        reinterpret_cast<float4*>(h)[(size_t)node * 32 + q] =
            reinterpret_cast<const float4*>(emb)[(size_t)x[node] * 32 + q];
    }
}

__global__ void k_count(const int* __restrict__ dst, int* __restrict__ deg, int e) {
    int i = blockIdx.x * blockDim.x + threadIdx.x;
    if (i < e) atomicAdd(&deg[dst[i]], 1);
}

// split + transpose weights to bf16 hi/lo: WT[n][k] = split(W[k][n])
__global__ void k_wsplit(const float* __restrict__ Wa, const float* __restrict__ Wb,
                         __nv_bfloat16* __restrict__ hi, __nv_bfloat16* __restrict__ lo) {
    int mat = blockIdx.x;   // 0..4 -> Wa[l], 5..9 -> Wb[l]
    const float* W = (mat < 5) ? (Wa + mat * 16384) : (Wb + (mat - 5) * 16384);
    __nv_bfloat16* H  = hi + mat * 16384;
    __nv_bfloat16* Lo = lo + mat * 16384;
    int nidx = threadIdx.x;
    for (int k = 0; k < 128; k++) {
        float x = W[k * 128 + nidx];
        __nv_bfloat16 h = __float2bfloat16(x);
        H[nidx * 128 + k]  = h;
        Lo[nidx * 128 + k] = __float2bfloat16(x - __bfloat162float(h));
    }
}

// ---- 3-phase scan -------------------------------------------------------------
__global__ void k_scan_blk(const int* __restrict__ deg, int* __restrict__ rowptr,
                           int* __restrict__ bsum, int n) {
    int i = blockIdx.x * SCAN_BLK + threadIdx.x;
    int lane = threadIdx.x & 31, wid = threadIdx.x >> 5;
    int v = (i < n) ? deg[i] : 0;
    int inc = v;
#pragma unroll
    for (int o = 1; o < 32; o <<= 1) {
        int t = __shfl_up_sync(0xFFFFFFFFu, inc, o);
        if (lane >= o) inc += t;
    }
    __shared__ int wsum[32];
    if (lane == 31) wsum[wid] = inc;
    __syncthreads();
    if (wid == 0) {
        int s = wsum[lane];
#pragma unroll
        for (int o = 1; o < 32; o <<= 1) {
            int t = __shfl_up_sync(0xFFFFFFFFu, s, o);
            if (lane >= o) s += t;
        }
        wsum[lane] = s;
    }
    __syncthreads();
    int base = (wid > 0) ? wsum[wid - 1] : 0;
    if (i < n) rowptr[i] = base + inc - v;
    if (threadIdx.x == SCAN_BLK - 1) bsum[blockIdx.x] = base + inc;
}

__global__ void k_scan_top(const int* __restrict__ bsum, int* __restrict__ boff,
                           int* __restrict__ total_out, int nb) {
    int t = threadIdx.x, lane = t & 31, wid = t >> 5;
    int v = (t < nb) ? bsum[t] : 0;
    int inc = v;
#pragma unroll
    for (int o = 1; o < 32; o <<= 1) {
        int u = __shfl_up_sync(0xFFFFFFFFu, inc, o);
        if (lane >= o) inc += u;
    }
    __shared__ int ws[32];
    __shared__ int wsx[33];
    if (lane == 31) ws[wid] = inc;
    __syncthreads();
    if (t == 0) {
        wsx[0] = 0;
        for (int w = 0; w < 4; w++) wsx[w + 1] = wsx[w] + ws[w];
    }
    __syncthreads();
    int excl = wsx[wid] + inc - v;
    if (t < nb) boff[t] = excl;
    if (t == blockDim.x - 1) *total_out = wsx[4];
}

__global__ void k_scan_add(int* __restrict__ rowptr, int* __restrict__ cursor,
                           const int* __restrict__ boff, int n) {
    int i = blockIdx.x * blockDim.x + threadIdx.x;
    if (i < n) {
        int r = rowptr[i] + boff[i >> 10];
        rowptr[i] = r;
        cursor[i] = r;
    }
}

__global__ void k_scatter(const int* __restrict__ src, const int* __restrict__ dst,
                          int* __restrict__ cursor, int* __restrict__ col, int e) {
    int i = blockIdx.x * blockDim.x + threadIdx.x;
    if (i < e) {
        int d = dst[i];
        int p = atomicAdd(&cursor[d], 1);
        col[p] = src[i];
    }
}

// z[n,:] = h[n,:] + sum neighbors
__global__ void k_agg(const float* __restrict__ h, const int* __restrict__ rowptr,
                      const int* __restrict__ col, float* __restrict__ z, int n) {
    int node = blockIdx.x * 4 + (threadIdx.x >> 5);
    if (node >= n) return;
    int lane = threadIdx.x & 31;
    const float4* h4 = reinterpret_cast<const float4*>(h);
    float4 acc = h4[(size_t)node * 32 + lane];
    int s0 = rowptr[node], s1 = rowptr[node + 1];
    int j = s0;
    for (; j + 1 < s1; j += 2) {
        int c0 = __ldg(&col[j]), c1 = __ldg(&col[j + 1]);
        float4 v0 = __ldg(&h4[(size_t)c0 * 32 + lane]);
        float4 v1 = __ldg(&h4[(size_t)c1 * 32 + lane]);
        acc.x += v0.x + v1.x; acc.y += v0.y + v1.y;
        acc.z += v0.z + v1.z; acc.w += v0.w + v1.w;
    }
    if (j < s1) {
        int c = __ldg(&col[j]);
        float4 v = __ldg(&h4[(size_t)c * 32 + lane]);
        acc.x += v.x; acc.y += v.y; acc.z += v.z; acc.w += v.w;
    }
    reinterpret_cast<float4*>(z)[(size_t)node * 32 + lane] = acc;
}

// ---------------- mma.sync GEMM: C = relu(Z @ W + bias) ----------------------
// Split-bf16: D = Zhi*Whi + Zhi*Wlo + Zlo*Whi via m16n8k16 HMMA.
// 256 threads = 8 warps (4m x 2n), block tile 128x128, K=128.
// SMEM (bf16 tiles, row stride 136 elems = 272 B):
#define TSTRIDE 136
#define TBYTES  (128 * TSTRIDE * 2)       // 34816
#define SM_ZHI  0
#define SM_ZLO  (SM_ZHI + TBYTES)
#define SM_WHI  (SM_ZLO + TBYTES)
#define SM_WLO  (SM_WHI + TBYTES)
#define SM_BIAS (SM_WLO + TBYTES)         // 139264
#define SMEM_MMA (SM_BIAS + 512)          // 139776

__device__ __forceinline__ uint32_t smem_u32(const void* p) {
    uint32_t a;
    asm("{ .reg .u64 t; cvta.to.shared.u64 t, %1; cvt.u32.u64 %0, t; }" : "=r"(a) : "l"(p));
    return a;
}

__device__ __forceinline__ void ldsm_x4(uint32_t* r, uint32_t addr) {
    asm volatile("ldmatrix.sync.aligned.m8n8.x4.shared.b16 {%0,%1,%2,%3}, [%4];"
        : "=r"(r[0]), "=r"(r[1]), "=r"(r[2]), "=r"(r[3]) : "r"(addr));
}

__device__ __forceinline__ void mma_16816(float* c, const uint32_t* a, const uint32_t* b) {
    asm volatile(
        "mma.sync.aligned.m16n8k16.row.col.f32.bf16.bf16.f32 "
        "{%0,%1,%2,%3}, {%4,%5,%6,%7}, {%8,%9}, {%0,%1,%2,%3};"
        : "+f"(c[0]), "+f"(c[1]), "+f"(c[2]), "+f"(c[3])
        : "r"(a[0]), "r"(a[1]), "r"(a[2]), "r"(a[3]), "r"(b[0]), "r"(b[1]));
}

__device__ __forceinline__ uint32_t pack_bf16x2(float a, float b) {
    __nv_bfloat162 t = __floats2bfloat162_rn(a, b);
    return *reinterpret_cast<uint32_t*>(&t);
}

__global__ __launch_bounds__(256, 1)
void k_gemm_mma(const float* __restrict__ Z,
                const uint4* __restrict__ WhiT, const uint4* __restrict__ WloT,
                const float* __restrict__ bias, float* __restrict__ C, int n) {
    extern __shared__ char sm[];
    const uint32_t sb = smem_u32(sm);
    const int tid = threadIdx.x;
    const int lane = tid & 31, w = tid >> 5;
    const int rowBase = blockIdx.x * 128;

    // ---- stage: each thread handles row = tid>>1, half = tid&1 (64 cols) ----
    {
        const int row = tid >> 1, half = tid & 1;
        const int gr = rowBase + row;
        // W tiles (bf16 [n][k] row-major in global): 8 uint4 per half-row
        const uint4* wh = WhiT + row * 16 + half * 8;
        const uint4* wl = WloT + row * 16 + half * 8;
        char* dh = sm + SM_WHI + row * 272 + half * 128;
        char* dl = sm + SM_WLO + row * 272 + half * 128;
#pragma unroll
        for (int j = 0; j < 8; j++) {
            reinterpret_cast<uint4*>(dh)[j] = __ldg(&wh[j]);
            reinterpret_cast<uint4*>(dl)[j] = __ldg(&wl[j]);
        }
        // Z tile: 16 float4 per half-row -> hi/lo bf16
        const float4* zr = reinterpret_cast<const float4*>(Z + (size_t)gr * 128) + half * 16;
        char* zh = sm + SM_ZHI + row * 272 + half * 128;
        char* zl = sm + SM_ZLO + row * 272 + half * 128;
#pragma unroll
        for (int j = 0; j < 16; j++) {
            float4 v = (gr < n) ? __ldg(&zr[j]) : make_float4(0.f, 0.f, 0.f, 0.f);
            uint2 hp, lp;
            hp.x = pack_bf16x2(v.x, v.y);
            hp.y = pack_bf16x2(v.z, v.w);
            float lx = v.x - __bfloat162float(__float2bfloat16(v.x));
            float ly = v.y - __bfloat162float(__float2bfloat16(v.y));
            float lz = v.z - __bfloat162float(__float2bfloat16(v.z));
            float lw = v.w - __bfloat162float(__float2bfloat16(v.w));
            lp.x = pack_bf16x2(lx, ly);
            lp.y = pack_bf16x2(lz, lw);
            reinterpret_cast<uint2*>(zh)[j] = hp;
            reinterpret_cast<uint2*>(zl)[j] = lp;
        }
        if (tid < 128) reinterpret_cast<float*>(sm + SM_BIAS)[tid] = bias[tid];
    }
    __syncthreads();

    // ---- compute: warp tile 32x64 at (m0, n0) ----
    const int m0 = (w >> 1) * 32, n0 = (w & 1) * 64;
    float acc[2][8][4];
#pragma unroll
    for (int a = 0; a < 2; a++)
#pragma unroll
        for (int b = 0; b < 8; b++)
#pragma unroll
            for (int c = 0; c < 4; c++) acc[a][b][c] = 0.f;

    // ldmatrix lane addressing
    const uint32_t a_row  = m0 + (lane & 15);
    const uint32_t a_coff = (lane >> 4) * 8;
    const uint32_t b_row  = n0 + ((lane >> 4) << 3) + (lane & 7);
    const uint32_t b_coff = ((lane >> 3) & 1) * 8;

#pragma unroll
    for (int ks = 0; ks < 8; ks++) {
        const int k = ks * 16;
        uint32_t ah[2][4], al[2][4];
#pragma unroll
        for (int mf = 0; mf < 2; mf++) {
            uint32_t addr = sb + SM_ZHI + (a_row + mf * 16) * 272 + (k + a_coff) * 2;
            ldsm_x4(ah[mf], addr);
            ldsm_x4(al[mf], addr + (SM_ZLO - SM_ZHI));
        }
#pragma unroll
        for (int nfg = 0; nfg < 4; nfg++) {
            uint32_t baddr = sb + SM_WHI + (b_row + nfg * 16) * 272 + (k + b_coff) * 2;
            uint32_t bh[4], bl[4];
            ldsm_x4(bh, baddr);
            ldsm_x4(bl, baddr + (SM_WLO - SM_WHI));
#pragma unroll
            for (int mf = 0; mf < 2; mf++) {
                mma_16816(acc[mf][nfg * 2 + 0], ah[mf], bh + 0);
                mma_16816(acc[mf][nfg * 2 + 0], al[mf], bh + 0);
                mma_16816(acc[mf][nfg * 2 + 0], ah[mf], bl + 0);
                mma_16816(acc[mf][nfg * 2 + 1], ah[mf], bh + 2);
                mma_16816(acc[mf][nfg * 2 + 1], al[mf], bh + 2);
                mma_16816(acc[mf][nfg * 2 + 1], ah[mf], bl + 2);
            }
        }
    }

    // ---- epilogue: bias + relu, float2 stores ----
    const float* bs = reinterpret_cast<const float*>(sm + SM_BIAS);
#pragma unroll
    for (int mf = 0; mf < 2; mf++) {
#pragma unroll
        for (int nf = 0; nf < 8; nf++) {
            int r = m0 + mf * 16 + (lane >> 2);
            int c = n0 + nf * 8 + (lane & 3) * 2;
            float b0 = bs[c], b1 = bs[c + 1];
            int gr0 = rowBase + r;
            if (gr0 < n) {
                float2 v;
                v.x = fmaxf(acc[mf][nf][0] + b0, 0.f);
                v.y = fmaxf(acc[mf][nf][1] + b1, 0.f);
                *reinterpret_cast<float2*>(C + (size_t)gr0 * 128 + c) = v;
            }
            int gr1 = gr0 + 8;
            if (gr1 < n) {
                float2 v;
                v.x = fmaxf(acc[mf][nf][2] + b0, 0.f);
                v.y = fmaxf(acc[mf][nf][3] + b1, 0.f);
                *reinterpret_cast<float2*>(C + (size_t)gr1 * 128 + c) = v;
            }
        }
    }
}

// ---------------- pool + final -------------------------------------------------
__global__ void k_pool_partial(const float* __restrict__ h, float* __restrict__ part, int n) {
    int d = threadIdx.x;
    float acc = 0.f;
    for (int r = blockIdx.x; r < n; r += gridDim.x)
        acc += h[(size_t)r * D + d];
    part[blockIdx.x * D + d] = acc;
}

__global__ void k_final(const float* __restrict__ part, const float* __restrict__ Wlin,
                        const float* __restrict__ blin, float* __restrict__ out) {
    __shared__ float pooled[D];
    int t = threadIdx.x;
    float acc = 0.f;
    for (int p = 0; p < NPART; p++) acc += part[p * D + t];
    pooled[t] = acc;
    __syncthreads();
    float o = blin[t];
    for (int d = 0; d < D; d++) o = fmaf(pooled[d], Wlin[d * D + t], o);
    out[t] = o;
}

// ---------------- launch -------------------------------------------------------
extern "C" void kernel_launch(void* const* d_in, const int* in_sizes, int n_in,
                              void* d_out, int out_size) {
    const int*   x    = (const int*)d_in[0];
    const int*   ei   = (const int*)d_in[1];
    const float* emb  = (const float*)d_in[2];
    const float* Wa   = (const float*)d_in[3];
    const float* ba   = (const float*)d_in[4];
    const float* Wb   = (const float*)d_in[5];
    const float* bb   = (const float*)d_in[6];
    const float* Wlin = (const float*)d_in[7];
    const float* blin = (const float*)d_in[8];
    float* out = (float*)d_out;

    const int N = in_sizes[0];
    const int E = in_sizes[1] / 2;
    const int* src = ei;
    const int* dst = ei + E;

    float *A, *B, *part;
    int *deg, *rowptr, *cursor, *col, *bsum, *boff;
    uint4 *whi, *wlo;
    cudaGetSymbolAddress((void**)&A, g_bufA);
    cudaGetSymbolAddress((void**)&B, g_bufB);
    cudaGetSymbolAddress((void**)&deg, g_deg);
    cudaGetSymbolAddress((void**)&rowptr, g_rowptr);
    cudaGetSymbolAddress((void**)&cursor, g_cursor);
    cudaGetSymbolAddress((void**)&col, g_col);
    cudaGetSymbolAddress((void**)&part, g_part);
    cudaGetSymbolAddress((void**)&bsum, g_bsum);
    cudaGetSymbolAddress((void**)&boff, g_boff);
    cudaGetSymbolAddress((void**)&whi, g_WhiT);
    cudaGetSymbolAddress((void**)&wlo, g_WloT);

    cudaFuncSetAttribute(k_gemm_mma, cudaFuncAttributeMaxDynamicSharedMemorySize, SMEM_MMA);

    // h = emb[x]
    k_gather<<<(N * 32 + 255) / 256, 256>>>(x, emb, A, N);

    // pre-split weights to transposed bf16 hi/lo
    k_wsplit<<<10, 128>>>(Wa, Wb, (__nv_bfloat16*)whi, (__nv_bfloat16*)wlo);

    // CSR build
    k_zero_int<<<(N + 255) / 256, 256>>>(deg, N);
    k_count<<<(E + 255) / 256, 256>>>(dst, deg, E);
    const int nb = (N + SCAN_BLK - 1) / SCAN_BLK;
    k_scan_blk<<<nb, SCAN_BLK>>>(deg, rowptr, bsum, N);
    k_scan_top<<<1, 128>>>(bsum, boff, rowptr + N, nb);
    k_scan_add<<<(N + 255) / 256, 256>>>(rowptr, cursor, boff, N);
    k_scatter<<<(E + 255) / 256, 256>>>(src, dst, cursor, col, E);

    const int gemm_blocks = (N + 127) / 128;
    const int agg_blocks  = (N + 3) / 4;
    for (int l = 0; l < L_LAYERS; l++) {
        k_agg<<<agg_blocks, 128>>>(A, rowptr, col, B, N);
        k_gemm_mma<<<gemm_blocks, 256, SMEM_MMA>>>(B, whi + (size_t)l * 2048,
                                                   wlo + (size_t)l * 2048, ba + l * D, A, N);
        k_gemm_mma<<<gemm_blocks, 256, SMEM_MMA>>>(A, whi + (size_t)(5 + l) * 2048,
                                                   wlo + (size_t)(5 + l) * 2048, bb + l * D, B, N);
        float* t = A; A = B; B = t;
    }

    k_pool_partial<<<NPART, 128>>>(A, part, N);
    k_final<<<1, 128>>>(part, Wlin, blin, out);
}